// round 4
// baseline (speedup 1.0000x reference)
#include <cuda_runtime.h>

#define B_   32
#define M_   64
#define A_   8400
#define TK   9
#define NC   80
#define EPSF 1e-9f
#define FINF 3.402823466e38f
#define IINF 0x7fffffff

// scratch (allocation-free): per-anchor positive count and min assigned gt
__device__ int g_count[B_ * A_];
__device__ int g_assign[B_ * A_];

__device__ __forceinline__ float iou_box(float gx1, float gy1, float gx2, float gy2,
                                         float bx1, float by1, float bx2, float by2) {
    // matches reference _iou: b1 = gt, b2 = other; denom = a1 + a2 - overlap + EPS
    float ix1 = fmaxf(gx1, bx1), iy1 = fmaxf(gy1, by1);
    float ix2 = fminf(gx2, bx2), iy2 = fminf(gy2, by2);
    float ov  = fmaxf(ix2 - ix1, 0.f) * fmaxf(iy2 - iy1, 0.f);
    float a1  = fmaxf(gx2 - gx1, 0.f) * fmaxf(gy2 - gy1, 0.f);
    float a2  = fmaxf(bx2 - bx1, 0.f) * fmaxf(by2 - by1, 0.f);
    return ov / (a1 + a2 - ov + EPSF);
}

__global__ void atss_init_kernel() {
    int i = blockIdx.x * 256 + threadIdx.x;
    if (i < B_ * A_) { g_count[i] = 0; g_assign[i] = IINF; }
}

// comparator: smaller distance wins; on tie, smaller index wins (lax.top_k semantics)
__device__ __forceinline__ bool better(float d1, int i1, float d2, int i2) {
    return (d1 < d2) || (d1 == d2 && i1 < i2);
}

// One block per (gt m, batch b). Finds top-9 closest anchors per FPN level,
// computes IoU threshold (mean + std ddof=1 over the 27 candidate IoUs), and
// scatters positives (iou > thr && center inside gt) into g_count/g_assign.
__global__ void __launch_bounds__(256) atss_topk_kernel(
    const float* __restrict__ anchors,    // [A,4]
    const float* __restrict__ gt_bboxes,  // [B,M,4]
    const float* __restrict__ pad_mask)   // [B,M,1]
{
    const int m = blockIdx.x;
    const int b = blockIdx.y;
    const int t = threadIdx.x;

    // padded gt contributes nothing (oh *= pad -> 0 everywhere)
    if (pad_mask[b * M_ + m] <= 0.f) return;   // uniform across block

    __shared__ float sd[256 * TK];
    __shared__ int   si[256 * TK];
    __shared__ float rd[256];
    __shared__ int   ri[256];
    __shared__ int   rs[256];
    __shared__ int   s_topi[3 * TK];
    __shared__ float s_iou[3 * TK];
    __shared__ float s_thr;

    float4 g = ((const float4*)gt_bboxes)[b * M_ + m];
    const float gx1 = g.x, gy1 = g.y, gx2 = g.z, gy2 = g.w;
    const float gcx = (gx1 + gx2) * 0.5f;
    const float gcy = (gy1 + gy2) * 0.5f;

    const int lstart[4] = {0, 6400, 8000, 8400};

    for (int lvl = 0; lvl < 3; lvl++) {
        // per-thread top-9 (register-resident, sorted ascending)
        float td[TK]; int ti[TK];
        #pragma unroll
        for (int k = 0; k < TK; k++) { td[k] = FINF; ti[k] = IINF; }

        const int s0 = lstart[lvl], s1 = lstart[lvl + 1];
        for (int i = s0 + t; i < s1; i += 256) {
            float4 ab = ((const float4*)anchors)[i];
            float acx = (ab.x + ab.z) * 0.5f;
            float acy = (ab.y + ab.w) * 0.5f;
            float dx = gcx - acx, dy = gcy - acy;
            float d = sqrtf(dx * dx + dy * dy);   // keep sqrt: rounding ties must match ref
            if (better(d, i, td[TK - 1], ti[TK - 1])) {
                td[TK - 1] = d; ti[TK - 1] = i;
                // single bubble-up pass (static indices -> stays in registers)
                #pragma unroll
                for (int k = TK - 1; k > 0; k--) {
                    if (better(td[k], ti[k], td[k - 1], ti[k - 1])) {
                        float fd = td[k]; td[k] = td[k - 1]; td[k - 1] = fd;
                        int   fi = ti[k]; ti[k] = ti[k - 1]; ti[k - 1] = fi;
                    }
                }
            }
        }
        #pragma unroll
        for (int k = 0; k < TK; k++) { sd[t * TK + k] = td[k]; si[t * TK + k] = ti[k]; }
        __syncthreads();

        // 9 rounds of block-wide argmin over the 2304 candidates
        for (int k = 0; k < TK; k++) {
            float bd = FINF; int bi = IINF; int bs = -1;
            for (int e = t; e < 256 * TK; e += 256) {
                float d = sd[e]; int ii = si[e];
                if (better(d, ii, bd, bi)) { bd = d; bi = ii; bs = e; }
            }
            rd[t] = bd; ri[t] = bi; rs[t] = bs;
            __syncthreads();
            for (int off = 128; off > 0; off >>= 1) {
                if (t < off) {
                    if (better(rd[t + off], ri[t + off], rd[t], ri[t])) {
                        rd[t] = rd[t + off]; ri[t] = ri[t + off]; rs[t] = rs[t + off];
                    }
                }
                __syncthreads();
            }
            if (t == 0) {
                s_topi[lvl * TK + k] = ri[0];
                sd[rs[0]] = FINF; si[rs[0]] = IINF;   // remove winner
            }
            __syncthreads();
        }
        __syncthreads();
    }

    // 27 candidate IoUs with the gt box
    if (t < 3 * TK) {
        float4 ab = ((const float4*)anchors)[s_topi[t]];
        s_iou[t] = iou_box(gx1, gy1, gx2, gy2, ab.x, ab.y, ab.z, ab.w);
    }
    __syncthreads();
    if (t == 0) {
        float mean = 0.f;
        #pragma unroll
        for (int k = 0; k < 3 * TK; k++) mean += s_iou[k];
        mean *= (1.f / 27.f);
        float var = 0.f;
        #pragma unroll
        for (int k = 0; k < 3 * TK; k++) { float dv = s_iou[k] - mean; var += dv * dv; }
        s_thr = mean + sqrtf(var * (1.f / 26.f));   // ddof=1
    }
    __syncthreads();

    if (t < 3 * TK) {
        if (s_iou[t] > s_thr) {
            int idx = s_topi[t];
            float4 ab = ((const float4*)anchors)[idx];
            float acx = (ab.x + ab.z) * 0.5f;
            float acy = (ab.y + ab.w) * 0.5f;
            float lmin = fminf(fminf(acx - gx1, acy - gy1), fminf(gx2 - acx, gy2 - acy));
            if (lmin > EPSF) {   // is_in_gts (strict > EPS)
                atomicAdd(&g_count[b * A_ + idx], 1);
                atomicMin(&g_assign[b * A_ + idx], m);   // argmax of 0/1 mask = min positive m
            }
        }
    }
}

// Thread-per-anchor finalize: resolve multi-assignments (argmax anchor-IoU over
// all 64 gts, first-occurrence ties), then write labels / bboxes / scores.
__global__ void __launch_bounds__(256) atss_assign_kernel(
    const float* __restrict__ anchors,    // [A,4]
    const int*   __restrict__ gt_labels,  // [B,M]
    const float* __restrict__ gt_bboxes,  // [B,M,4]
    const float* __restrict__ pred,       // [B,A,4]
    const int*   __restrict__ bg_ptr,     // [1] or null
    float*       __restrict__ out)
{
    const int b  = blockIdx.y;
    const int a0 = blockIdx.x * 256;
    const int t  = threadIdx.x;
    const int a  = a0 + t;

    __shared__ float4 s_gt[M_];
    __shared__ int    s_lab[M_];
    if (t < M_) {
        s_gt[t]  = ((const float4*)gt_bboxes)[b * M_ + t];
        s_lab[t] = gt_labels[b * M_ + t];
    }

    const long long OFF1 = (long long)B_ * A_;          // bboxes offset
    const long long OFF2 = OFF1 + (long long)B_ * A_ * 4; // scores offset

    // coalesced float4 zero-fill of this block's score rows
    int nA = A_ - a0; if (nA > 256) nA = 256;
    float4* srow = (float4*)(out + OFF2 + ((long long)b * A_ + a0) * NC);
    const int nvec = nA * NC / 4;
    for (int i = t; i < nvec; i += 256) srow[i] = make_float4(0.f, 0.f, 0.f, 0.f);
    __syncthreads();

    if (a >= A_) return;
    const long long ba = (long long)b * A_ + a;
    const int bg = bg_ptr ? bg_ptr[0] : NC;

    int cnt = g_count[ba];
    int asg = (cnt == 1) ? g_assign[ba] : 0;

    if (cnt > 1) {
        // replaced by is_max_iou column: argmax over m of anchor-iou, first-max ties
        float4 ab = ((const float4*)anchors)[a];
        float best = -1.f; int bm = 0;
        #pragma unroll 4
        for (int mm = 0; mm < M_; mm++) {
            float4 gg = s_gt[mm];
            float v = iou_box(gg.x, gg.y, gg.z, gg.w, ab.x, ab.y, ab.z, ab.w);
            if (v > best) { best = v; bm = mm; }
        }
        asg = bm;
    }

    int   label = bg;
    float sval  = 0.f;
    if (cnt > 0) {
        label = s_lab[asg];
        float4 p = ((const float4*)pred)[ba];
        float4 gg = s_gt[asg];
        sval = iou_box(gg.x, gg.y, gg.z, gg.w, p.x, p.y, p.z, p.w);
    }

    out[ba] = (float)label;                         // assigned_labels (as f32)
    ((float4*)(out + OFF1))[ba] = s_gt[asg];        // assigned_bboxes (index 0 when bg)
    if (cnt > 0 && label >= 0 && label < NC)
        out[OFF2 + ba * NC + label] = sval;         // one-hot * max(pious)
}

extern "C" void kernel_launch(void* const* d_in, const int* in_sizes, int n_in,
                              void* d_out, int out_size) {
    const float* anchors   = (const float*)d_in[0];
    const int*   gt_labels = (const int*)d_in[1];
    const float* gt_bboxes = (const float*)d_in[2];
    const float* pad_mask  = (const float*)d_in[3];
    const float* pred      = (const float*)d_in[4];
    const int*   bg_ptr    = (n_in > 5) ? (const int*)d_in[5] : nullptr;
    float* out = (float*)d_out;

    atss_init_kernel<<<(B_ * A_ + 255) / 256, 256>>>();
    atss_topk_kernel<<<dim3(M_, B_), 256>>>(anchors, gt_bboxes, pad_mask);
    atss_assign_kernel<<<dim3((A_ + 255) / 256, B_), 256>>>(
        anchors, gt_labels, gt_bboxes, pred, bg_ptr, out);
}

// round 5
// speedup vs baseline: 6.9220x; 6.9220x over previous
#include <cuda_runtime.h>

#define B_   32
#define M_   64
#define A_   8400
#define TK   9
#define NC   80
#define EPSF 1e-9f
#define IINF 0x7fffffff

// scratch (allocation-free): per-anchor positive count and min assigned gt
__device__ int g_count[B_ * A_];
__device__ int g_assign[B_ * A_];

__device__ __forceinline__ float iou_box(float gx1, float gy1, float gx2, float gy2,
                                         float bx1, float by1, float bx2, float by2) {
    // matches reference _iou: b1 = gt, b2 = other; denom = a1 + a2 - overlap + EPS
    float ix1 = fmaxf(gx1, bx1), iy1 = fmaxf(gy1, by1);
    float ix2 = fminf(gx2, bx2), iy2 = fminf(gy2, by2);
    float ov  = fmaxf(ix2 - ix1, 0.f) * fmaxf(iy2 - iy1, 0.f);
    float a1  = fmaxf(gx2 - gx1, 0.f) * fmaxf(gy2 - gy1, 0.f);
    float a2  = fmaxf(bx2 - bx1, 0.f) * fmaxf(by2 - by1, 0.f);
    return ov / (a1 + a2 - ov + EPSF);
}

// vectorized scratch clear: 268800 ints per array -> 67200 int4 per array
__global__ void atss_init_kernel() {
    int i = blockIdx.x * 256 + threadIdx.x;
    if (i < (B_ * A_) / 4) {
        ((int4*)g_count)[i]  = make_int4(0, 0, 0, 0);
        ((int4*)g_assign)[i] = make_int4(IINF, IINF, IINF, IINF);
    }
}

// One WARP per (b,m). Anchors are regular grids, so the top-9-by-center-distance
// per FPN level is contained in the 5x5 grid window around the gt center
// (9th-nearest lattice distance <= 1.581*stride < 2.0*stride = min excluded
// distance). Selection = 9 rounds of warp-min over u64 (d2,idx) keys — exact
// lax.top_k tie-break, no sqrt needed (only the SET of top-9 is consumed, and
// d2-order refines sqrt-order). Then thr = mean + std(ddof=1) over the 27
// candidate IoUs (sequential sum order identical to the previous passing
// kernel), and positives are scattered via atomics.
__global__ void __launch_bounds__(256) atss_topk_kernel(
    const float* __restrict__ anchors,    // [A,4]
    const float* __restrict__ gt_bboxes,  // [B,M,4]
    const float* __restrict__ pad_mask)   // [B,M,1]
{
    const int warp = threadIdx.x >> 5;
    const int lane = threadIdx.x & 31;
    const int wid  = blockIdx.x * 8 + warp;   // (b,m) flat, 2048 total
    const int b = wid >> 6;
    const int m = wid & 63;

    if (pad_mask[wid] <= 0.f) return;         // warp-uniform

    const float4 g = ((const float4*)gt_bboxes)[wid];
    const float gcx = (g.x + g.z) * 0.5f;
    const float gcy = (g.y + g.w) * 0.5f;

    const int   FS[3]   = {80, 40, 20};
    const float INV[3]  = {0.125f, 0.0625f, 0.03125f};  // 1/stride (exact pow2)
    const int   BASE[3] = {0, 6400, 8000};

    int my_win = 0;          // lane r (< 27) ends up holding winner lvl*9 + r
    bool have_win = false;

    #pragma unroll
    for (int lvl = 0; lvl < 3; lvl++) {
        const int fs = FS[lvl];
        const int base = BASE[lvl];
        int jx0 = (int)floorf(gcx * INV[lvl] - 0.5f) - 2;
        int iy0 = (int)floorf(gcy * INV[lvl] - 0.5f) - 2;
        jx0 = min(max(jx0, 0), fs - 5);
        iy0 = min(max(iy0, 0), fs - 5);

        unsigned long long key = ~0ull;
        if (lane < 25) {
            const int idx = base + (iy0 + lane / 5) * fs + (jx0 + lane % 5);
            float4 ab = ((const float4*)anchors)[idx];
            float acx = (ab.x + ab.z) * 0.5f;
            float acy = (ab.y + ab.w) * 0.5f;
            float dx = gcx - acx, dy = gcy - acy;
            float d2 = dx * dx + dy * dy;       // nonneg -> bit pattern is order-preserving
            key = ((unsigned long long)__float_as_uint(d2) << 32) | (unsigned)idx;
        }

        #pragma unroll
        for (int r = 0; r < TK; r++) {
            unsigned long long mn = key;
            #pragma unroll
            for (int off = 16; off; off >>= 1) {
                unsigned long long o = __shfl_xor_sync(0xffffffffu, mn, off);
                if (o < mn) mn = o;
            }
            if (key == mn) key = ~0ull;         // winner drops out (keys unique)
            if (lane == lvl * TK + r) { my_win = (int)(mn & 0xffffffffu); have_win = true; }
        }
    }

    // IoU of the 27 winners with the gt box
    float my_iou = 0.f;
    float4 ab = make_float4(0.f, 0.f, 0.f, 0.f);
    if (have_win) {
        ab = ((const float4*)anchors)[my_win];
        my_iou = iou_box(g.x, g.y, g.z, g.w, ab.x, ab.y, ab.z, ab.w);
    }

    // mean + std (ddof=1), sequential order r = 0..26 (matches prior passing kernel)
    float mean = 0.f;
    #pragma unroll
    for (int r = 0; r < 27; r++) mean += __shfl_sync(0xffffffffu, my_iou, r);
    mean *= (1.f / 27.f);
    float var = 0.f;
    #pragma unroll
    for (int r = 0; r < 27; r++) {
        float v = __shfl_sync(0xffffffffu, my_iou, r) - mean;
        var += v * v;
    }
    const float thr = mean + sqrtf(var * (1.f / 26.f));

    if (have_win && my_iou > thr) {
        float acx = (ab.x + ab.z) * 0.5f;
        float acy = (ab.y + ab.w) * 0.5f;
        float lmin = fminf(fminf(acx - g.x, acy - g.y), fminf(g.z - acx, g.w - acy));
        if (lmin > EPSF) {                      // is_in_gts (strict > EPS)
            atomicAdd(&g_count[b * A_ + my_win], 1);
            atomicMin(&g_assign[b * A_ + my_win], m);  // argmax of 0/1 mask = min positive m
        }
    }
}

// Thread-per-anchor finalize: resolve multi-assignments (argmax anchor-IoU over
// all 64 gts, first-occurrence ties), then write labels / bboxes / scores.
__global__ void __launch_bounds__(256) atss_assign_kernel(
    const float* __restrict__ anchors,    // [A,4]
    const int*   __restrict__ gt_labels,  // [B,M]
    const float* __restrict__ gt_bboxes,  // [B,M,4]
    const float* __restrict__ pred,       // [B,A,4]
    const int*   __restrict__ bg_ptr,     // [1] or null
    float*       __restrict__ out)
{
    const int b  = blockIdx.y;
    const int a0 = blockIdx.x * 256;
    const int t  = threadIdx.x;
    const int a  = a0 + t;

    __shared__ float4 s_gt[M_];
    __shared__ int    s_lab[M_];
    if (t < M_) {
        s_gt[t]  = ((const float4*)gt_bboxes)[b * M_ + t];
        s_lab[t] = gt_labels[b * M_ + t];
    }

    const long long OFF1 = (long long)B_ * A_;            // bboxes offset
    const long long OFF2 = OFF1 + (long long)B_ * A_ * 4; // scores offset

    // coalesced float4 zero-fill of this block's score rows
    int nA = A_ - a0; if (nA > 256) nA = 256;
    float4* srow = (float4*)(out + OFF2 + ((long long)b * A_ + a0) * NC);
    const int nvec = nA * NC / 4;
    for (int i = t; i < nvec; i += 256) srow[i] = make_float4(0.f, 0.f, 0.f, 0.f);
    __syncthreads();

    if (a >= A_) return;
    const long long ba = (long long)b * A_ + a;
    const int bg = bg_ptr ? bg_ptr[0] : NC;

    int cnt = g_count[ba];
    int asg = (cnt == 1) ? g_assign[ba] : 0;

    if (cnt > 1) {
        // replaced by is_max_iou column: argmax over m of anchor-iou, first-max ties
        float4 ab = ((const float4*)anchors)[a];
        float best = -1.f; int bm = 0;
        #pragma unroll 4
        for (int mm = 0; mm < M_; mm++) {
            float4 gg = s_gt[mm];
            float v = iou_box(gg.x, gg.y, gg.z, gg.w, ab.x, ab.y, ab.z, ab.w);
            if (v > best) { best = v; bm = mm; }
        }
        asg = bm;
    }

    int   label = bg;
    float sval  = 0.f;
    if (cnt > 0) {
        label = s_lab[asg];
        float4 p = ((const float4*)pred)[ba];
        float4 gg = s_gt[asg];
        sval = iou_box(gg.x, gg.y, gg.z, gg.w, p.x, p.y, p.z, p.w);
    }

    out[ba] = (float)label;                         // assigned_labels (as f32)
    ((float4*)(out + OFF1))[ba] = s_gt[asg];        // assigned_bboxes (gt[0] when bg)
    if (cnt > 0 && label >= 0 && label < NC)
        out[OFF2 + ba * NC + label] = sval;         // one-hot * max(pious)
}

extern "C" void kernel_launch(void* const* d_in, const int* in_sizes, int n_in,
                              void* d_out, int out_size) {
    const float* anchors   = (const float*)d_in[0];
    const int*   gt_labels = (const int*)d_in[1];
    const float* gt_bboxes = (const float*)d_in[2];
    const float* pad_mask  = (const float*)d_in[3];
    const float* pred      = (const float*)d_in[4];
    const int*   bg_ptr    = (n_in > 5) ? (const int*)d_in[5] : nullptr;
    float* out = (float*)d_out;

    atss_init_kernel<<<((B_ * A_) / 4 + 255) / 256, 256>>>();
    atss_topk_kernel<<<(B_ * M_) / 8, 256>>>(anchors, gt_bboxes, pad_mask);
    atss_assign_kernel<<<dim3((A_ + 255) / 256, B_), 256>>>(
        anchors, gt_labels, gt_bboxes, pred, bg_ptr, out);
}

// round 7
// speedup vs baseline: 6.9673x; 1.0065x over previous
#include <cuda_runtime.h>

#define B_   32
#define M_   64
#define A_   8400
#define TK   9
#define NC   80
#define EPSF 1e-9f

// scratch (allocation-free, zero after each use-cycle's clear kernel):
// packed per-anchor tag: bits[31:16] = positive count, bits[15:0] = sum of (m+1).
// count<=64 and sum(m+1) <= 64*64 = 4096 < 65536, so no overflow across fields.
// When count==1 the low half is exactly m+1; when count>1 we recompute anyway.
__device__ int g_tag[B_ * A_];

__device__ __forceinline__ float iou_box(float gx1, float gy1, float gx2, float gy2,
                                         float bx1, float by1, float bx2, float by2) {
    // matches reference _iou: b1 = gt, b2 = other; denom = a1 + a2 - overlap + EPS
    float ix1 = fmaxf(gx1, bx1), iy1 = fmaxf(gy1, by1);
    float ix2 = fminf(gx2, bx2), iy2 = fminf(gy2, by2);
    float ov  = fmaxf(ix2 - ix1, 0.f) * fmaxf(iy2 - iy1, 0.f);
    float a1  = fmaxf(gx2 - gx1, 0.f) * fmaxf(gy2 - gy1, 0.f);
    float a2  = fmaxf(bx2 - bx1, 0.f) * fmaxf(by2 - by1, 0.f);
    return ov / (a1 + a2 - ov + EPSF);
}

// Pure streaming zero-fill: the 86 MB scores region of the output + the 1 MB
// scratch tag array. Nothing else — lets the store path run at the LTS cap.
#define NSCORE4  ((B_ * A_ * NC) / 4)          // 5,376,000 float4
#define NTAG4    ((B_ * A_) / 4)               // 67,200 int4
#define NCLR     (NSCORE4 + NTAG4)
__global__ void __launch_bounds__(256) atss_clear_kernel(float4* __restrict__ scores4) {
    const float4 z = make_float4(0.f, 0.f, 0.f, 0.f);
    int4* tag4 = (int4*)g_tag;
    for (long long i = (long long)blockIdx.x * 256 + threadIdx.x; i < NCLR;
         i += (long long)gridDim.x * 256) {
        if (i < NSCORE4) scores4[i] = z;
        else ((int4*)tag4)[i - NSCORE4] = make_int4(0, 0, 0, 0);
    }
}

// One WARP per (b,m). Anchors are regular grids, so the top-9-by-center-distance
// per FPN level is contained in the 5x5 grid window around the gt center
// (9th-nearest lattice distance <= 1.581*stride < 2.0*stride = min excluded
// distance). Selection = 9 rounds of warp-min over u64 (d2,idx) keys — exact
// lax.top_k tie-break (d2-order refines sqrt-order; only the SET is consumed).
// thr = mean + std(ddof=1) over the 27 candidate IoUs, sequential order r=0..26
// (bit-identical to the R4 passing kernel). Positives scatter one packed atomic.
__global__ void __launch_bounds__(256) atss_topk_kernel(
    const float* __restrict__ anchors,    // [A,4]
    const float* __restrict__ gt_bboxes,  // [B,M,4]
    const float* __restrict__ pad_mask)   // [B,M,1]
{
    const int warp = threadIdx.x >> 5;
    const int lane = threadIdx.x & 31;
    const int wid  = blockIdx.x * 8 + warp;   // (b,m) flat, 2048 total
    const int b = wid >> 6;
    const int m = wid & 63;

    if (pad_mask[wid] <= 0.f) return;         // warp-uniform

    const float4 g = ((const float4*)gt_bboxes)[wid];
    const float gcx = (g.x + g.z) * 0.5f;
    const float gcy = (g.y + g.w) * 0.5f;

    const int   FS[3]   = {80, 40, 20};
    const float INV[3]  = {0.125f, 0.0625f, 0.03125f};  // 1/stride (exact pow2)
    const int   BASE[3] = {0, 6400, 8000};

    int my_win = 0;          // lane r (< 27) ends up holding winner lvl*9 + r
    bool have_win = false;

    #pragma unroll
    for (int lvl = 0; lvl < 3; lvl++) {
        const int fs = FS[lvl];
        const int base = BASE[lvl];
        int jx0 = (int)floorf(gcx * INV[lvl] - 0.5f) - 2;
        int iy0 = (int)floorf(gcy * INV[lvl] - 0.5f) - 2;
        jx0 = min(max(jx0, 0), fs - 5);
        iy0 = min(max(iy0, 0), fs - 5);

        unsigned long long key = ~0ull;
        if (lane < 25) {
            const int idx = base + (iy0 + lane / 5) * fs + (jx0 + lane % 5);
            float4 ab = ((const float4*)anchors)[idx];
            float acx = (ab.x + ab.z) * 0.5f;
            float acy = (ab.y + ab.w) * 0.5f;
            float dx = gcx - acx, dy = gcy - acy;
            float d2 = dx * dx + dy * dy;       // nonneg -> bit pattern is order-preserving
            key = ((unsigned long long)__float_as_uint(d2) << 32) | (unsigned)idx;
        }

        #pragma unroll
        for (int r = 0; r < TK; r++) {
            unsigned long long mn = key;
            #pragma unroll
            for (int off = 16; off; off >>= 1) {
                unsigned long long o = __shfl_xor_sync(0xffffffffu, mn, off);
                if (o < mn) mn = o;
            }
            if (key == mn) key = ~0ull;         // winner drops out (keys unique)
            if (lane == lvl * TK + r) { my_win = (int)(mn & 0xffffffffu); have_win = true; }
        }
    }

    // IoU of the 27 winners with the gt box
    float my_iou = 0.f;
    float4 ab = make_float4(0.f, 0.f, 0.f, 0.f);
    if (have_win) {
        ab = ((const float4*)anchors)[my_win];
        my_iou = iou_box(g.x, g.y, g.z, g.w, ab.x, ab.y, ab.z, ab.w);
    }

    // mean + std (ddof=1), sequential order r = 0..26 (matches prior passing kernel)
    float mean = 0.f;
    #pragma unroll
    for (int r = 0; r < 27; r++) mean += __shfl_sync(0xffffffffu, my_iou, r);
    mean *= (1.f / 27.f);
    float var = 0.f;
    #pragma unroll
    for (int r = 0; r < 27; r++) {
        float v = __shfl_sync(0xffffffffu, my_iou, r) - mean;
        var += v * v;
    }
    const float thr = mean + sqrtf(var * (1.f / 26.f));

    if (have_win && my_iou > thr) {
        float acx = (ab.x + ab.z) * 0.5f;
        float acy = (ab.y + ab.w) * 0.5f;
        float lmin = fminf(fminf(acx - g.x, acy - g.y), fminf(g.z - acx, g.w - acy));
        if (lmin > EPSF) {                      // is_in_gts (strict > EPS)
            atomicAdd(&g_tag[b * A_ + my_win], 0x10000 + m + 1);
        }
    }
}

// Thread-per-anchor finalize: resolve multi-assignments (argmax anchor-IoU over
// all 64 gts, first-occurrence ties), then write labels / bboxes / sparse score.
// Scores region already zeroed by the clear kernel.
__global__ void __launch_bounds__(256) atss_assign_kernel(
    const float* __restrict__ anchors,    // [A,4]
    const int*   __restrict__ gt_labels,  // [B,M]
    const float* __restrict__ gt_bboxes,  // [B,M,4]
    const float* __restrict__ pred,       // [B,A,4]
    const int*   __restrict__ bg_ptr,     // [1] or null
    float*       __restrict__ out)
{
    const int b = blockIdx.y;
    const int t = threadIdx.x;
    const int a = blockIdx.x * 256 + t;

    __shared__ float4 s_gt[M_];
    __shared__ int    s_lab[M_];
    if (t < M_) {
        s_gt[t]  = ((const float4*)gt_bboxes)[b * M_ + t];
        s_lab[t] = gt_labels[b * M_ + t];
    }
    __syncthreads();

    if (a >= A_) return;
    const long long OFF1 = (long long)B_ * A_;            // bboxes offset
    const long long OFF2 = OFF1 + (long long)B_ * A_ * 4; // scores offset
    const long long ba = (long long)b * A_ + a;
    const int bg = bg_ptr ? bg_ptr[0] : NC;

    const int tag = g_tag[ba];
    const int cnt = tag >> 16;
    int asg = (cnt == 1) ? (tag & 0xffff) - 1 : 0;

    if (cnt > 1) {
        // mask_multi -> is_max_iou column: argmax over m of anchor-iou, first-max ties
        float4 ab = ((const float4*)anchors)[a];
        float best = -1.f; int bm = 0;
        #pragma unroll 4
        for (int mm = 0; mm < M_; mm++) {
            float4 gg = s_gt[mm];
            float v = iou_box(gg.x, gg.y, gg.z, gg.w, ab.x, ab.y, ab.z, ab.w);
            if (v > best) { best = v; bm = mm; }
        }
        asg = bm;
    }

    int   label = bg;
    float sval  = 0.f;
    if (cnt > 0) {
        label = s_lab[asg];
        float4 p = ((const float4*)pred)[ba];
        float4 gg = s_gt[asg];
        sval = iou_box(gg.x, gg.y, gg.z, gg.w, p.x, p.y, p.z, p.w);
    }

    out[ba] = (float)label;                         // assigned_labels (as f32)
    ((float4*)(out + OFF1))[ba] = s_gt[asg];        // assigned_bboxes (gt[0] when bg)
    if (cnt > 0 && label >= 0 && label < NC)
        out[OFF2 + ba * NC + label] = sval;         // one-hot * max(pious)
}

extern "C" void kernel_launch(void* const* d_in, const int* in_sizes, int n_in,
                              void* d_out, int out_size) {
    const float* anchors   = (const float*)d_in[0];
    const int*   gt_labels = (const int*)d_in[1];
    const float* gt_bboxes = (const float*)d_in[2];
    const float* pad_mask  = (const float*)d_in[3];
    const float* pred      = (const float*)d_in[4];
    const int*   bg_ptr    = (n_in > 5) ? (const int*)d_in[5] : nullptr;
    float* out = (float*)d_out;

    const long long OFF2 = (long long)B_ * A_ * 5;  // labels + bboxes
    atss_clear_kernel<<<2048, 256>>>((float4*)(out + OFF2));
    atss_topk_kernel<<<(B_ * M_) / 8, 256>>>(anchors, gt_bboxes, pad_mask);
    atss_assign_kernel<<<dim3((A_ + 255) / 256, B_), 256>>>(
        anchors, gt_labels, gt_bboxes, pred, bg_ptr, out);
}